// round 1
// baseline (speedup 1.0000x reference)
#include <cuda_runtime.h>
#include <math.h>

// Problem dims (fixed by the problem)
#define BB 2
#define TT 2048
#define CC 1024
#define HH 16
#define DD 64
#define C3 3072
#define MM (BB * TT)   // 4096

// Scratch (device globals; no allocation allowed)
__device__ float g_qkv[(size_t)MM * C3];   // [4096][3072]  q|k|v
__device__ float g_y[(size_t)MM * CC];     // [4096][1024]  attention output, [b,t,h*64+d]

// ---------------------------------------------------------------------------
// Generic fp32 GEMM: C[M,N] = A[M,K] @ B[N,K]^T   (both row-major, K contiguous)
// Block tile 128x128, K-tile 16, 256 threads, 8x8 per-thread micro-tile.
// M,N multiples of 128; K multiple of 16. All true here (4096/3072/1024).
// ---------------------------------------------------------------------------
__global__ void __launch_bounds__(256) gemm_abt(const float* __restrict__ A,
                                                const float* __restrict__ Bm,
                                                float* __restrict__ Cm,
                                                int M, int N, int K) {
    __shared__ float As[16][132];
    __shared__ float Bs[16][132];

    const int tid = threadIdx.x;
    const int bm = blockIdx.y * 128;
    const int bn = blockIdx.x * 128;
    const int tx = tid & 15;   // n dimension
    const int ty = tid >> 4;   // m dimension

    const float* Ap = A + (size_t)bm * K;
    const float* Bp = Bm + (size_t)bn * K;

    float acc[8][8];
#pragma unroll
    for (int i = 0; i < 8; i++)
#pragma unroll
        for (int j = 0; j < 8; j++) acc[i][j] = 0.f;

    for (int k0 = 0; k0 < K; k0 += 16) {
        // Load 128x16 A tile and 128x16 B tile (transposed into smem: [k][row])
#pragma unroll
        for (int i = 0; i < 2; i++) {
            int f = tid + i * 256;      // 0..511 float4 slots
            int row = f >> 2;           // 0..127
            int kk = (f & 3) << 2;      // 0,4,8,12
            float4 va = *(const float4*)(Ap + (size_t)row * K + k0 + kk);
            As[kk + 0][row] = va.x; As[kk + 1][row] = va.y;
            As[kk + 2][row] = va.z; As[kk + 3][row] = va.w;
            float4 vb = *(const float4*)(Bp + (size_t)row * K + k0 + kk);
            Bs[kk + 0][row] = vb.x; Bs[kk + 1][row] = vb.y;
            Bs[kk + 2][row] = vb.z; Bs[kk + 3][row] = vb.w;
        }
        __syncthreads();

#pragma unroll
        for (int k = 0; k < 16; k++) {
            float a[8], b[8];
            *(float4*)&a[0] = *(const float4*)&As[k][ty * 8];
            *(float4*)&a[4] = *(const float4*)&As[k][ty * 8 + 4];
            *(float4*)&b[0] = *(const float4*)&Bs[k][tx * 8];
            *(float4*)&b[4] = *(const float4*)&Bs[k][tx * 8 + 4];
#pragma unroll
            for (int i = 0; i < 8; i++)
#pragma unroll
                for (int j = 0; j < 8; j++)
                    acc[i][j] = fmaf(a[i], b[j], acc[i][j]);
        }
        __syncthreads();
    }

#pragma unroll
    for (int i = 0; i < 8; i++) {
        float* crow = Cm + (size_t)(bm + ty * 8 + i) * N + bn + tx * 8;
        float4 v0 = make_float4(acc[i][0], acc[i][1], acc[i][2], acc[i][3]);
        float4 v1 = make_float4(acc[i][4], acc[i][5], acc[i][6], acc[i][7]);
        *(float4*)(crow) = v0;
        *(float4*)(crow + 4) = v1;
    }
}

// ---------------------------------------------------------------------------
// Flash attention (causal), fp32.
// Grid: (T/64, H, B). Block: 128 threads.
// Per-block: 64 query rows. Thread (rg = tid>>3, cg = tid&7) owns
//   rows r_i = rg + 16*i (i=0..3)  and  cols/dims cg*8..cg*8+7.
// K tiles streamed; online softmax; P staged through smem for the O GEMM.
// Smem swizzles chosen for conflict-free LDS.128 (see XOR patterns below).
// ---------------------------------------------------------------------------
#define ATTN_SMEM_FLOATS (3 * 64 * 68 + 64 * 65)
#define ATTN_SMEM_BYTES (ATTN_SMEM_FLOATS * 4)

__global__ void __launch_bounds__(128) attn_kernel(const float* __restrict__ qkv,
                                                   float* __restrict__ y) {
    extern __shared__ float sm[];
    float* Qs = sm;                    // [64][68]
    float* Ks = sm + 64 * 68;          // [64][68], cols d XOR'ed by 4*(c>>3)
    float* Vs = sm + 2 * 64 * 68;      // [64][68], cols d XOR'ed by (d&32)>>3
    float* Ps = sm + 3 * 64 * 68;      // [64][65], scalar access

    const int qt = blockIdx.x;
    const int h  = blockIdx.y;
    const int b  = blockIdx.z;
    const int tid = threadIdx.x;
    const int rg = tid >> 3;   // 0..15
    const int cg = tid & 7;    // 0..7

    const size_t baseQ = (size_t)b * TT * C3 + (size_t)h * DD;
    const size_t baseK = baseQ + CC;
    const size_t baseV = baseQ + 2 * CC;

    // Load Q tile (rows qt*64 .. +63), plain layout
#pragma unroll
    for (int it = 0; it < 8; it++) {
        int f = tid + it * 128;          // 0..1023 float4 slots
        int row = f >> 4;                // 0..63
        int d4 = (f & 15) << 2;          // 0..60
        float4 v = *(const float4*)(qkv + baseQ + (size_t)(qt * 64 + row) * C3 + d4);
        *(float4*)&Qs[row * 68 + d4] = v;
    }

    float m[4], l[4], o[4][8];
#pragma unroll
    for (int i = 0; i < 4; i++) {
        m[i] = -1e30f; l[i] = 0.f;
#pragma unroll
        for (int j = 0; j < 8; j++) o[i][j] = 0.f;
    }

    // Precompute swizzled V read offsets for this thread's d-range
    const int d0 = cg * 8;
    const int dv0 = d0 ^ ((d0 & 32) >> 3);
    const int d1 = cg * 8 + 4;
    const int dv1 = d1 ^ ((d1 & 32) >> 3);

    for (int kt = 0; kt <= qt; kt++) {
        __syncthreads();   // prior V-GEMM readers done before overwriting Ks/Vs

        // Load K, V tiles (keys kt*64 .. +63) with swizzled smem stores
#pragma unroll
        for (int it = 0; it < 8; it++) {
            int f = tid + it * 128;
            int c = f >> 4;
            int d4 = (f & 15) << 2;
            float4 kv = *(const float4*)(qkv + baseK + (size_t)(kt * 64 + c) * C3 + d4);
            *(float4*)&Ks[c * 68 + (d4 ^ ((c >> 3) << 2))] = kv;
            float4 vv = *(const float4*)(qkv + baseV + (size_t)(kt * 64 + c) * C3 + d4);
            *(float4*)&Vs[c * 68 + (d4 ^ ((d4 & 32) >> 3))] = vv;
        }
        __syncthreads();

        // S = Q @ K^T for this thread's 4x8 S tile
        float s[4][8];
#pragma unroll
        for (int i = 0; i < 4; i++)
#pragma unroll
            for (int j = 0; j < 8; j++) s[i][j] = 0.f;

#pragma unroll
        for (int d4 = 0; d4 < 64; d4 += 4) {
            float4 q4[4];
#pragma unroll
            for (int i = 0; i < 4; i++)
                q4[i] = *(const float4*)&Qs[(rg + 16 * i) * 68 + d4];
#pragma unroll
            for (int j = 0; j < 8; j++) {
                int c = cg * 8 + j;
                float4 k4 = *(const float4*)&Ks[c * 68 + (d4 ^ (cg << 2))];
#pragma unroll
                for (int i = 0; i < 4; i++) {
                    s[i][j] = fmaf(q4[i].x, k4.x, s[i][j]);
                    s[i][j] = fmaf(q4[i].y, k4.y, s[i][j]);
                    s[i][j] = fmaf(q4[i].z, k4.z, s[i][j]);
                    s[i][j] = fmaf(q4[i].w, k4.w, s[i][j]);
                }
            }
        }

        // Scale + causal mask (only on diagonal tile)
        const bool diag = (kt == qt);
#pragma unroll
        for (int i = 0; i < 4; i++) {
            int r = rg + 16 * i;
#pragma unroll
            for (int j = 0; j < 8; j++) {
                int c = cg * 8 + j;
                float sv = s[i][j] * 0.125f;   // 1/sqrt(64)
                if (diag && c > r) sv = -1e30f;
                s[i][j] = sv;
            }
        }

        // Online softmax per row (8 threads per row: lanes cg=0..7, consecutive)
#pragma unroll
        for (int i = 0; i < 4; i++) {
            float mx = s[i][0];
#pragma unroll
            for (int j = 1; j < 8; j++) mx = fmaxf(mx, s[i][j]);
            mx = fmaxf(mx, __shfl_xor_sync(0xffffffffu, mx, 1));
            mx = fmaxf(mx, __shfl_xor_sync(0xffffffffu, mx, 2));
            mx = fmaxf(mx, __shfl_xor_sync(0xffffffffu, mx, 4));
            float mnew = fmaxf(m[i], mx);
            float corr = __expf(m[i] - mnew);
            float ls = 0.f;
#pragma unroll
            for (int j = 0; j < 8; j++) {
                float p = __expf(s[i][j] - mnew);
                s[i][j] = p;
                ls += p;
            }
            ls += __shfl_xor_sync(0xffffffffu, ls, 1);
            ls += __shfl_xor_sync(0xffffffffu, ls, 2);
            ls += __shfl_xor_sync(0xffffffffu, ls, 4);
            l[i] = l[i] * corr + ls;
            m[i] = mnew;
#pragma unroll
            for (int j = 0; j < 8; j++) o[i][j] *= corr;
            int r = rg + 16 * i;
#pragma unroll
            for (int j = 0; j < 8; j++) Ps[r * 65 + cg * 8 + j] = s[i][j];
        }
        __syncthreads();

        // O += P @ V  (thread's 4 rows x 8 dims)
#pragma unroll 4
        for (int c = 0; c < 64; c++) {
            float4 v0 = *(const float4*)&Vs[c * 68 + dv0];
            float4 v1 = *(const float4*)&Vs[c * 68 + dv1];
            float pr[4];
#pragma unroll
            for (int i = 0; i < 4; i++) pr[i] = Ps[(rg + 16 * i) * 65 + c];
#pragma unroll
            for (int i = 0; i < 4; i++) {
                float p = pr[i];
                o[i][0] = fmaf(p, v0.x, o[i][0]);
                o[i][1] = fmaf(p, v0.y, o[i][1]);
                o[i][2] = fmaf(p, v0.z, o[i][2]);
                o[i][3] = fmaf(p, v0.w, o[i][3]);
                o[i][4] = fmaf(p, v1.x, o[i][4]);
                o[i][5] = fmaf(p, v1.y, o[i][5]);
                o[i][6] = fmaf(p, v1.z, o[i][6]);
                o[i][7] = fmaf(p, v1.w, o[i][7]);
            }
        }
    }

    // Epilogue: normalize and write y in [b, t, h*64+d] layout
#pragma unroll
    for (int i = 0; i < 4; i++) {
        int r = rg + 16 * i;
        float invl = 1.f / l[i];
        float4 w0 = make_float4(o[i][0] * invl, o[i][1] * invl, o[i][2] * invl, o[i][3] * invl);
        float4 w1 = make_float4(o[i][4] * invl, o[i][5] * invl, o[i][6] * invl, o[i][7] * invl);
        size_t addr = ((size_t)b * TT + (size_t)qt * 64 + r) * CC + (size_t)h * DD + cg * 8;
        *(float4*)(y + addr) = w0;
        *(float4*)(y + addr + 4) = w1;
    }
}

// ---------------------------------------------------------------------------
extern "C" void kernel_launch(void* const* d_in, const int* in_sizes, int n_in,
                              void* d_out, int out_size) {
    const float* x      = (const float*)d_in[0];   // [2,2048,1024]
    const float* w_attn = (const float*)d_in[1];   // [3072,1024]
    const float* w_proj = (const float*)d_in[2];   // [1024,1024]
    float* out = (float*)d_out;                    // [2,2048,1024]

    void* qkv_p = nullptr;
    void* y_p = nullptr;
    cudaGetSymbolAddress(&qkv_p, g_qkv);
    cudaGetSymbolAddress(&y_p, g_y);
    float* qkv = (float*)qkv_p;
    float* yb  = (float*)y_p;

    // 1) QKV = x @ w_attn^T   : [4096,3072]
    gemm_abt<<<dim3(C3 / 128, MM / 128), 256>>>(x, w_attn, qkv, MM, C3, CC);

    // 2) Flash attention -> y [4096,1024]
    cudaFuncSetAttribute(attn_kernel, cudaFuncAttributeMaxDynamicSharedMemorySize,
                         ATTN_SMEM_BYTES);
    attn_kernel<<<dim3(TT / 64, HH, BB), 128, ATTN_SMEM_BYTES>>>(qkv, yb);

    // 3) out = y @ w_proj^T   : [4096,1024]
    gemm_abt<<<dim3(CC / 128, MM / 128), 256>>>(yb, w_proj, out, MM, CC, CC);
}

// round 3
// speedup vs baseline: 1.5435x; 1.5435x over previous
#include <cuda_runtime.h>
#include <cuda_bf16.h>
#include <cstdint>
#include <math.h>

// Problem dims
#define BB 2
#define TT 2048
#define CC 1024
#define HH 16
#define DD 64
#define C3 3072
#define MM (BB * TT)   // 4096

// ---------------------------------------------------------------------------
// Scratch (device globals; no allocation allowed)
// ---------------------------------------------------------------------------
__device__ float g_qkv[(size_t)MM * C3];                 // fp32 q|k|v
__device__ float g_y[(size_t)MM * CC];                   // fp32 attn out
__device__ __nv_bfloat16 g_xh[(size_t)MM * CC];
__device__ __nv_bfloat16 g_xl[(size_t)MM * CC];
__device__ __nv_bfloat16 g_wah[(size_t)C3 * CC];
__device__ __nv_bfloat16 g_wal[(size_t)C3 * CC];
__device__ __nv_bfloat16 g_wph[(size_t)CC * CC];
__device__ __nv_bfloat16 g_wpl[(size_t)CC * CC];
__device__ __nv_bfloat16 g_yh[(size_t)MM * CC];
__device__ __nv_bfloat16 g_yl[(size_t)MM * CC];

// ---------------------------------------------------------------------------
// Helpers (sm_103 base-target only: ldmatrix / mma.sync / cp.async)
// ---------------------------------------------------------------------------
__device__ __forceinline__ uint32_t smem_to_u32(const void* p) {
    uint32_t a;
    asm("{ .reg .u64 t; cvta.to.shared.u64 t, %1; cvt.u32.u64 %0, t; }"
        : "=r"(a) : "l"(p));
    return a;
}

#define SWZ(off) ((off) ^ (((off) >> 3) & 0x70))

__device__ __forceinline__ void cp16(uint32_t saddr, const void* g) {
    asm volatile("cp.async.cg.shared.global [%0], [%1], 16;"
                 :: "r"(saddr), "l"(g));
}
#define CP_COMMIT() asm volatile("cp.async.commit_group;" ::: "memory")
#define CP_WAIT(n)  asm volatile("cp.async.wait_group %0;" :: "n"(n) : "memory")

#define LDSM4(r, addr) \
    asm volatile("ldmatrix.sync.aligned.m8n8.x4.shared.b16 {%0,%1,%2,%3}, [%4];" \
        : "=r"((r)[0]), "=r"((r)[1]), "=r"((r)[2]), "=r"((r)[3]) : "r"(addr))

#define MMA16816(d, a, b0v, b1v) \
    asm volatile("mma.sync.aligned.m16n8k16.row.col.f32.bf16.bf16.f32 " \
        "{%0,%1,%2,%3}, {%4,%5,%6,%7}, {%8,%9}, {%0,%1,%2,%3};" \
        : "+f"((d)[0]), "+f"((d)[1]), "+f"((d)[2]), "+f"((d)[3]) \
        : "r"((a)[0]), "r"((a)[1]), "r"((a)[2]), "r"((a)[3]), "r"(b0v), "r"(b1v))

// ---------------------------------------------------------------------------
// Split fp32 -> bf16 hi/lo planes (v = hi + lo + O(2^-17 |v|))
// ---------------------------------------------------------------------------
__global__ void __launch_bounds__(256) split_f32(const float* __restrict__ in,
                                                 __nv_bfloat16* __restrict__ hi,
                                                 __nv_bfloat16* __restrict__ lo,
                                                 int n4) {
    int i = blockIdx.x * 256 + threadIdx.x;
    if (i >= n4) return;
    float4 v = ((const float4*)in)[i];
    __nv_bfloat16 h0 = __float2bfloat16(v.x);
    __nv_bfloat16 h1 = __float2bfloat16(v.y);
    __nv_bfloat16 h2 = __float2bfloat16(v.z);
    __nv_bfloat16 h3 = __float2bfloat16(v.w);
    __nv_bfloat16 l0 = __float2bfloat16(v.x - __bfloat162float(h0));
    __nv_bfloat16 l1 = __float2bfloat16(v.y - __bfloat162float(h1));
    __nv_bfloat16 l2 = __float2bfloat16(v.z - __bfloat162float(h2));
    __nv_bfloat16 l3 = __float2bfloat16(v.w - __bfloat162float(h3));
    ((__nv_bfloat162*)hi)[i * 2 + 0] = __nv_bfloat162(h0, h1);
    ((__nv_bfloat162*)hi)[i * 2 + 1] = __nv_bfloat162(h2, h3);
    ((__nv_bfloat162*)lo)[i * 2 + 0] = __nv_bfloat162(l0, l1);
    ((__nv_bfloat162*)lo)[i * 2 + 1] = __nv_bfloat162(l2, l3);
}

// ---------------------------------------------------------------------------
// HMMA GEMM: C[M,N] = A[M,K] @ B[N,K]^T, fp32-accurate via bf16 3-term split.
// Tile 128x128, K-chunk 32, 256 threads (8 warps = 4m x 2n), warp tile 32x64.
// Smem: per stage, A-pair [128 rows][hi 64B | lo 64B] + B-pair same = 32KB.
// Double buffered (64KB), cp.async pipelined.
// ---------------------------------------------------------------------------
#define STAGE_BYTES 32768
#define GEMM_SMEM (2 * STAGE_BYTES)

__global__ void __launch_bounds__(256) gemm_hmma3(
    const __nv_bfloat16* __restrict__ Ah, const __nv_bfloat16* __restrict__ Al,
    const __nv_bfloat16* __restrict__ Bh, const __nv_bfloat16* __restrict__ Bl,
    float* __restrict__ C, int M, int N, int K) {
    extern __shared__ char smem[];
    const uint32_t sbase = smem_to_u32(smem);
    const int tid = threadIdx.x;
    const int lane = tid & 31;
    const int wid = tid >> 5;
    const int wm = wid >> 1;       // 0..3
    const int wn = wid & 1;        // 0..1
    const int bm = blockIdx.y * 128;
    const int bn = blockIdx.x * 128;

    float acc[2][8][4];
#pragma unroll
    for (int i = 0; i < 2; i++)
#pragma unroll
        for (int j = 0; j < 8; j++)
#pragma unroll
            for (int t = 0; t < 4; t++) acc[i][j][t] = 0.f;

    const int nch = K >> 5;
    const int rowL = tid >> 3;     // 0..31 (iter adds 32)
    const int uL = tid & 7;        // 16B unit: 0-3 hi, 4-7 lo

    auto ld_chunk = [&](int c, int st) {
        const int k0 = c << 5;
        const uint32_t sA = sbase + st * STAGE_BYTES;
        const uint32_t sB = sA + 16384;
        const int kk = k0 + (uL & 3) * 8;
        const bool isHi = (uL < 4);
        const __nv_bfloat16* gA = (isHi ? Ah : Al);
        const __nv_bfloat16* gB = (isHi ? Bh : Bl);
#pragma unroll
        for (int it = 0; it < 4; it++) {
            int row = rowL + it * 32;
            cp16(sA + SWZ(row * 128 + uL * 16), gA + (size_t)(bm + row) * K + kk);
            cp16(sB + SWZ(row * 128 + uL * 16), gB + (size_t)(bn + row) * K + kk);
        }
    };

    auto compute = [&](int st) {
        const uint32_t sA = sbase + st * STAGE_BYTES;
        const uint32_t sB = sA + 16384;
#pragma unroll
        for (int ks = 0; ks < 2; ks++) {
            uint32_t ah[2][4], al[2][4];
            const int rA = lane & 15;
            const int uA = ks * 2 + (lane >> 4);   // 16B unit within hi half
#pragma unroll
            for (int mi = 0; mi < 2; mi++) {
                int mrow = wm * 32 + mi * 16 + rA;
                LDSM4(ah[mi], sA + SWZ(mrow * 128 + uA * 16));
                LDSM4(al[mi], sA + SWZ(mrow * 128 + (uA + 4) * 16));
            }
            const int rB = (lane & 7) + ((lane & 16) >> 1);
            const int uB = ks * 2 + ((lane & 8) >> 3);
#pragma unroll
            for (int nb = 0; nb < 4; nb++) {
                int nrow = wn * 64 + nb * 16 + rB;
                uint32_t bh[4], bl[4];
                LDSM4(bh, sB + SWZ(nrow * 128 + uB * 16));
                LDSM4(bl, sB + SWZ(nrow * 128 + (uB + 4) * 16));
#pragma unroll
                for (int mi = 0; mi < 2; mi++) {
                    MMA16816(acc[mi][nb * 2 + 0], ah[mi], bh[0], bh[1]);
                    MMA16816(acc[mi][nb * 2 + 1], ah[mi], bh[2], bh[3]);
                    MMA16816(acc[mi][nb * 2 + 0], ah[mi], bl[0], bl[1]);
                    MMA16816(acc[mi][nb * 2 + 1], ah[mi], bl[2], bl[3]);
                    MMA16816(acc[mi][nb * 2 + 0], al[mi], bh[0], bh[1]);
                    MMA16816(acc[mi][nb * 2 + 1], al[mi], bh[2], bh[3]);
                }
            }
        }
    };

    ld_chunk(0, 0);
    CP_COMMIT();
    for (int c = 0; c < nch; c++) {
        if (c + 1 < nch) {
            ld_chunk(c + 1, (c + 1) & 1);
            CP_COMMIT();
            CP_WAIT(1);
        } else {
            CP_WAIT(0);
        }
        __syncthreads();
        compute(c & 1);
        __syncthreads();
    }

    // Epilogue: acc -> C (fp32)
    const int er = lane >> 2;
    const int ec = (lane & 3) * 2;
#pragma unroll
    for (int mi = 0; mi < 2; mi++) {
#pragma unroll
        for (int nj = 0; nj < 8; nj++) {
            int row = bm + wm * 32 + mi * 16 + er;
            int col = bn + wn * 64 + nj * 8 + ec;
            float2 v0 = make_float2(acc[mi][nj][0], acc[mi][nj][1]);
            float2 v1 = make_float2(acc[mi][nj][2], acc[mi][nj][3]);
            *(float2*)(C + (size_t)row * N + col) = v0;
            *(float2*)(C + (size_t)(row + 8) * N + col) = v1;
        }
    }
}

// ---------------------------------------------------------------------------
// Flash attention (causal), fp32 — unchanged from round 1 (passes @ ~590us).
// ---------------------------------------------------------------------------
#define ATTN_SMEM_FLOATS (3 * 64 * 68 + 64 * 65)
#define ATTN_SMEM_BYTES (ATTN_SMEM_FLOATS * 4)

__global__ void __launch_bounds__(128) attn_kernel(const float* __restrict__ qkv,
                                                   float* __restrict__ y) {
    extern __shared__ float sm[];
    float* Qs = sm;
    float* Ks = sm + 64 * 68;
    float* Vs = sm + 2 * 64 * 68;
    float* Ps = sm + 3 * 64 * 68;

    const int qt = blockIdx.x;
    const int h  = blockIdx.y;
    const int b  = blockIdx.z;
    const int tid = threadIdx.x;
    const int rg = tid >> 3;
    const int cg = tid & 7;

    const size_t baseQ = (size_t)b * TT * C3 + (size_t)h * DD;
    const size_t baseK = baseQ + CC;
    const size_t baseV = baseQ + 2 * CC;

#pragma unroll
    for (int it = 0; it < 8; it++) {
        int f = tid + it * 128;
        int row = f >> 4;
        int d4 = (f & 15) << 2;
        float4 v = *(const float4*)(qkv + baseQ + (size_t)(qt * 64 + row) * C3 + d4);
        *(float4*)&Qs[row * 68 + d4] = v;
    }

    float m[4], l[4], o[4][8];
#pragma unroll
    for (int i = 0; i < 4; i++) {
        m[i] = -1e30f; l[i] = 0.f;
#pragma unroll
        for (int j = 0; j < 8; j++) o[i][j] = 0.f;
    }

    const int d0 = cg * 8;
    const int dv0 = d0 ^ ((d0 & 32) >> 3);
    const int d1 = cg * 8 + 4;
    const int dv1 = d1 ^ ((d1 & 32) >> 3);

    for (int kt = 0; kt <= qt; kt++) {
        __syncthreads();
#pragma unroll
        for (int it = 0; it < 8; it++) {
            int f = tid + it * 128;
            int c = f >> 4;
            int d4 = (f & 15) << 2;
            float4 kv = *(const float4*)(qkv + baseK + (size_t)(kt * 64 + c) * C3 + d4);
            *(float4*)&Ks[c * 68 + (d4 ^ ((c >> 3) << 2))] = kv;
            float4 vv = *(const float4*)(qkv + baseV + (size_t)(kt * 64 + c) * C3 + d4);
            *(float4*)&Vs[c * 68 + (d4 ^ ((d4 & 32) >> 3))] = vv;
        }
        __syncthreads();

        float s[4][8];
#pragma unroll
        for (int i = 0; i < 4; i++)
#pragma unroll
            for (int j = 0; j < 8; j++) s[i][j] = 0.f;

#pragma unroll
        for (int d4 = 0; d4 < 64; d4 += 4) {
            float4 q4[4];
#pragma unroll
            for (int i = 0; i < 4; i++)
                q4[i] = *(const float4*)&Qs[(rg + 16 * i) * 68 + d4];
#pragma unroll
            for (int j = 0; j < 8; j++) {
                int c = cg * 8 + j;
                float4 k4 = *(const float4*)&Ks[c * 68 + (d4 ^ (cg << 2))];
#pragma unroll
                for (int i = 0; i < 4; i++) {
                    s[i][j] = fmaf(q4[i].x, k4.x, s[i][j]);
                    s[i][j] = fmaf(q4[i].y, k4.y, s[i][j]);
                    s[i][j] = fmaf(q4[i].z, k4.z, s[i][j]);
                    s[i][j] = fmaf(q4[i].w, k4.w, s[i][j]);
                }
            }
        }

        const bool diag = (kt == qt);
#pragma unroll
        for (int i = 0; i < 4; i++) {
            int r = rg + 16 * i;
#pragma unroll
            for (int j = 0; j < 8; j++) {
                int c = cg * 8 + j;
                float sv = s[i][j] * 0.125f;
                if (diag && c > r) sv = -1e30f;
                s[i][j] = sv;
            }
        }

#pragma unroll
        for (int i = 0; i < 4; i++) {
            float mx = s[i][0];
#pragma unroll
            for (int j = 1; j < 8; j++) mx = fmaxf(mx, s[i][j]);
            mx = fmaxf(mx, __shfl_xor_sync(0xffffffffu, mx, 1));
            mx = fmaxf(mx, __shfl_xor_sync(0xffffffffu, mx, 2));
            mx = fmaxf(mx, __shfl_xor_sync(0xffffffffu, mx, 4));
            float mnew = fmaxf(m[i], mx);
            float corr = __expf(m[i] - mnew);
            float ls = 0.f;
#pragma unroll
            for (int j = 0; j < 8; j++) {
                float p = __expf(s[i][j] - mnew);
                s[i][j] = p;
                ls += p;
            }
            ls += __shfl_xor_sync(0xffffffffu, ls, 1);
            ls += __shfl_xor_sync(0xffffffffu, ls, 2);
            ls += __shfl_xor_sync(0xffffffffu, ls, 4);
            l[i] = l[i] * corr + ls;
            m[i] = mnew;
#pragma unroll
            for (int j = 0; j < 8; j++) o[i][j] *= corr;
            int r = rg + 16 * i;
#pragma unroll
            for (int j = 0; j < 8; j++) Ps[r * 65 + cg * 8 + j] = s[i][j];
        }
        __syncthreads();

#pragma unroll 4
        for (int c = 0; c < 64; c++) {
            float4 v0 = *(const float4*)&Vs[c * 68 + dv0];
            float4 v1 = *(const float4*)&Vs[c * 68 + dv1];
            float pr[4];
#pragma unroll
            for (int i = 0; i < 4; i++) pr[i] = Ps[(rg + 16 * i) * 65 + c];
#pragma unroll
            for (int i = 0; i < 4; i++) {
                float p = pr[i];
                o[i][0] = fmaf(p, v0.x, o[i][0]);
                o[i][1] = fmaf(p, v0.y, o[i][1]);
                o[i][2] = fmaf(p, v0.z, o[i][2]);
                o[i][3] = fmaf(p, v0.w, o[i][3]);
                o[i][4] = fmaf(p, v1.x, o[i][4]);
                o[i][5] = fmaf(p, v1.y, o[i][5]);
                o[i][6] = fmaf(p, v1.z, o[i][6]);
                o[i][7] = fmaf(p, v1.w, o[i][7]);
            }
        }
    }

#pragma unroll
    for (int i = 0; i < 4; i++) {
        int r = rg + 16 * i;
        float invl = 1.f / l[i];
        float4 w0 = make_float4(o[i][0] * invl, o[i][1] * invl, o[i][2] * invl, o[i][3] * invl);
        float4 w1 = make_float4(o[i][4] * invl, o[i][5] * invl, o[i][6] * invl, o[i][7] * invl);
        size_t addr = ((size_t)b * TT + (size_t)qt * 64 + r) * CC + (size_t)h * DD + cg * 8;
        *(float4*)(y + addr) = w0;
        *(float4*)(y + addr + 4) = w1;
    }
}

// ---------------------------------------------------------------------------
extern "C" void kernel_launch(void* const* d_in, const int* in_sizes, int n_in,
                              void* d_out, int out_size) {
    const float* x      = (const float*)d_in[0];
    const float* w_attn = (const float*)d_in[1];
    const float* w_proj = (const float*)d_in[2];
    float* out = (float*)d_out;

    void *qkv_p, *y_p, *xh_p, *xl_p, *wah_p, *wal_p, *wph_p, *wpl_p, *yh_p, *yl_p;
    cudaGetSymbolAddress(&qkv_p, g_qkv);
    cudaGetSymbolAddress(&y_p, g_y);
    cudaGetSymbolAddress(&xh_p, g_xh);
    cudaGetSymbolAddress(&xl_p, g_xl);
    cudaGetSymbolAddress(&wah_p, g_wah);
    cudaGetSymbolAddress(&wal_p, g_wal);
    cudaGetSymbolAddress(&wph_p, g_wph);
    cudaGetSymbolAddress(&wpl_p, g_wpl);
    cudaGetSymbolAddress(&yh_p, g_yh);
    cudaGetSymbolAddress(&yl_p, g_yl);
    float* qkv = (float*)qkv_p;
    float* yb  = (float*)y_p;

    cudaFuncSetAttribute(gemm_hmma3, cudaFuncAttributeMaxDynamicSharedMemorySize,
                         GEMM_SMEM);
    cudaFuncSetAttribute(attn_kernel, cudaFuncAttributeMaxDynamicSharedMemorySize,
                         ATTN_SMEM_BYTES);

    // 1) Split inputs into bf16 hi/lo planes
    split_f32<<<(MM * CC / 4 + 255) / 256, 256>>>(x, (__nv_bfloat16*)xh_p,
                                                  (__nv_bfloat16*)xl_p, MM * CC / 4);
    split_f32<<<(C3 * CC / 4 + 255) / 256, 256>>>(w_attn, (__nv_bfloat16*)wah_p,
                                                  (__nv_bfloat16*)wal_p, C3 * CC / 4);
    split_f32<<<(CC * CC / 4 + 255) / 256, 256>>>(w_proj, (__nv_bfloat16*)wph_p,
                                                  (__nv_bfloat16*)wpl_p, CC * CC / 4);

    // 2) QKV = x @ w_attn^T : [4096, 3072]
    gemm_hmma3<<<dim3(C3 / 128, MM / 128), 256, GEMM_SMEM>>>(
        (const __nv_bfloat16*)xh_p, (const __nv_bfloat16*)xl_p,
        (const __nv_bfloat16*)wah_p, (const __nv_bfloat16*)wal_p,
        qkv, MM, C3, CC);

    // 3) Flash attention -> y [4096, 1024]
    attn_kernel<<<dim3(TT / 64, HH, BB), 128, ATTN_SMEM_BYTES>>>(qkv, yb);

    // 4) Split y
    split_f32<<<(MM * CC / 4 + 255) / 256, 256>>>(yb, (__nv_bfloat16*)yh_p,
                                                  (__nv_bfloat16*)yl_p, MM * CC / 4);

    // 5) out = y @ w_proj^T : [4096, 1024]
    gemm_hmma3<<<dim3(CC / 128, MM / 128), 256, GEMM_SMEM>>>(
        (const __nv_bfloat16*)yh_p, (const __nv_bfloat16*)yl_p,
        (const __nv_bfloat16*)wph_p, (const __nv_bfloat16*)wpl_p,
        out, MM, CC, CC);
}

// round 4
// speedup vs baseline: 2.5713x; 1.6659x over previous
#include <cuda_runtime.h>
#include <cuda_bf16.h>
#include <cstdint>
#include <math.h>

// Problem dims
#define BB 2
#define TT 2048
#define CC 1024
#define HH 16
#define DD 64
#define C3 3072
#define MM (BB * TT)   // 4096

// ---------------------------------------------------------------------------
// Scratch (device globals; no allocation allowed)
// ---------------------------------------------------------------------------
__device__ __nv_bfloat16 g_xh[(size_t)MM * CC];
__device__ __nv_bfloat16 g_xl[(size_t)MM * CC];
__device__ __nv_bfloat16 g_wah[(size_t)C3 * CC];
__device__ __nv_bfloat16 g_wal[(size_t)C3 * CC];
__device__ __nv_bfloat16 g_wph[(size_t)CC * CC];
__device__ __nv_bfloat16 g_wpl[(size_t)CC * CC];
__device__ __nv_bfloat16 g_qkvh[(size_t)MM * C3];
__device__ __nv_bfloat16 g_qkvl[(size_t)MM * C3];
__device__ __nv_bfloat16 g_yh[(size_t)MM * CC];
__device__ __nv_bfloat16 g_yl[(size_t)MM * CC];

// ---------------------------------------------------------------------------
// Helpers (sm_103 base-target: ldmatrix / mma.sync / cp.async)
// ---------------------------------------------------------------------------
__device__ __forceinline__ uint32_t smem_to_u32(const void* p) {
    uint32_t a;
    asm("{ .reg .u64 t; cvta.to.shared.u64 t, %1; cvt.u32.u64 %0, t; }"
        : "=r"(a) : "l"(p));
    return a;
}

#define SWZ(off) ((off) ^ (((off) >> 3) & 0x70))

__device__ __forceinline__ void cp16(uint32_t saddr, const void* g) {
    asm volatile("cp.async.cg.shared.global [%0], [%1], 16;"
                 :: "r"(saddr), "l"(g));
}
#define CP_COMMIT() asm volatile("cp.async.commit_group;" ::: "memory")
#define CP_WAIT(n)  asm volatile("cp.async.wait_group %0;" :: "n"(n) : "memory")

#define LDSM4(r, addr) \
    asm volatile("ldmatrix.sync.aligned.m8n8.x4.shared.b16 {%0,%1,%2,%3}, [%4];" \
        : "=r"((r)[0]), "=r"((r)[1]), "=r"((r)[2]), "=r"((r)[3]) : "r"(addr))

#define LDSM4T(r, addr) \
    asm volatile("ldmatrix.sync.aligned.m8n8.x4.trans.shared.b16 {%0,%1,%2,%3}, [%4];" \
        : "=r"((r)[0]), "=r"((r)[1]), "=r"((r)[2]), "=r"((r)[3]) : "r"(addr))

#define MMA16816(d, a, b0v, b1v) \
    asm volatile("mma.sync.aligned.m16n8k16.row.col.f32.bf16.bf16.f32 " \
        "{%0,%1,%2,%3}, {%4,%5,%6,%7}, {%8,%9}, {%0,%1,%2,%3};" \
        : "+f"((d)[0]), "+f"((d)[1]), "+f"((d)[2]), "+f"((d)[3]) \
        : "r"((a)[0]), "r"((a)[1]), "r"((a)[2]), "r"((a)[3]), "r"(b0v), "r"(b1v))

__device__ __forceinline__ uint32_t pack_bf16x2(float a, float b) {
    __nv_bfloat162 t = __floats2bfloat162_rn(a, b);
    return *(uint32_t*)&t;
}

// ---------------------------------------------------------------------------
// Split fp32 -> bf16 hi/lo planes
// ---------------------------------------------------------------------------
__global__ void __launch_bounds__(256) split_f32(const float* __restrict__ in,
                                                 __nv_bfloat16* __restrict__ hi,
                                                 __nv_bfloat16* __restrict__ lo,
                                                 int n4) {
    int i = blockIdx.x * 256 + threadIdx.x;
    if (i >= n4) return;
    float4 v = ((const float4*)in)[i];
    __nv_bfloat16 h0 = __float2bfloat16(v.x);
    __nv_bfloat16 h1 = __float2bfloat16(v.y);
    __nv_bfloat16 h2 = __float2bfloat16(v.z);
    __nv_bfloat16 h3 = __float2bfloat16(v.w);
    __nv_bfloat16 l0 = __float2bfloat16(v.x - __bfloat162float(h0));
    __nv_bfloat16 l1 = __float2bfloat16(v.y - __bfloat162float(h1));
    __nv_bfloat16 l2 = __float2bfloat16(v.z - __bfloat162float(h2));
    __nv_bfloat16 l3 = __float2bfloat16(v.w - __bfloat162float(h3));
    ((__nv_bfloat162*)hi)[i * 2 + 0] = __nv_bfloat162(h0, h1);
    ((__nv_bfloat162*)hi)[i * 2 + 1] = __nv_bfloat162(h2, h3);
    ((__nv_bfloat162*)lo)[i * 2 + 0] = __nv_bfloat162(l0, l1);
    ((__nv_bfloat162*)lo)[i * 2 + 1] = __nv_bfloat162(l2, l3);
}

// ---------------------------------------------------------------------------
// HMMA GEMM: C[M,N] = A[M,K] @ B[N,K]^T, fp32-accurate via bf16 3-term split.
// Tile 128x128, K-chunk 32, 8 warps (4m x 2n), warp tile 32x64, double buffer.
// SPLIT=true: write bf16 hi/lo planes (scaling cols<1024 by 0.125 for Q).
// ---------------------------------------------------------------------------
#define STAGE_BYTES 32768
#define GEMM_SMEM (2 * STAGE_BYTES)

template <bool SPLIT>
__global__ void __launch_bounds__(256) gemm_hmma3(
    const __nv_bfloat16* __restrict__ Ah, const __nv_bfloat16* __restrict__ Al,
    const __nv_bfloat16* __restrict__ Bh, const __nv_bfloat16* __restrict__ Bl,
    float* __restrict__ C, __nv_bfloat16* __restrict__ Ch,
    __nv_bfloat16* __restrict__ Cl, int M, int N, int K) {
    extern __shared__ char smem[];
    const uint32_t sbase = smem_to_u32(smem);
    const int tid = threadIdx.x;
    const int lane = tid & 31;
    const int wid = tid >> 5;
    const int wm = wid >> 1;
    const int wn = wid & 1;
    const int bm = blockIdx.y * 128;
    const int bn = blockIdx.x * 128;

    float acc[2][8][4];
#pragma unroll
    for (int i = 0; i < 2; i++)
#pragma unroll
        for (int j = 0; j < 8; j++)
#pragma unroll
            for (int t = 0; t < 4; t++) acc[i][j][t] = 0.f;

    const int nch = K >> 5;
    const int rowL = tid >> 3;
    const int uL = tid & 7;

    auto ld_chunk = [&](int c, int st) {
        const int k0 = c << 5;
        const uint32_t sA = sbase + st * STAGE_BYTES;
        const uint32_t sB = sA + 16384;
        const int kk = k0 + (uL & 3) * 8;
        const bool isHi = (uL < 4);
        const __nv_bfloat16* gA = (isHi ? Ah : Al);
        const __nv_bfloat16* gB = (isHi ? Bh : Bl);
#pragma unroll
        for (int it = 0; it < 4; it++) {
            int row = rowL + it * 32;
            cp16(sA + SWZ(row * 128 + uL * 16), gA + (size_t)(bm + row) * K + kk);
            cp16(sB + SWZ(row * 128 + uL * 16), gB + (size_t)(bn + row) * K + kk);
        }
    };

    auto compute = [&](int st) {
        const uint32_t sA = sbase + st * STAGE_BYTES;
        const uint32_t sB = sA + 16384;
#pragma unroll
        for (int ks = 0; ks < 2; ks++) {
            uint32_t ah[2][4], al[2][4];
            const int rA = lane & 15;
            const int uA = ks * 2 + (lane >> 4);
#pragma unroll
            for (int mi = 0; mi < 2; mi++) {
                int mrow = wm * 32 + mi * 16 + rA;
                LDSM4(ah[mi], sA + SWZ(mrow * 128 + uA * 16));
                LDSM4(al[mi], sA + SWZ(mrow * 128 + (uA + 4) * 16));
            }
            const int rB = (lane & 7) + ((lane & 16) >> 1);
            const int uB = ks * 2 + ((lane & 8) >> 3);
#pragma unroll
            for (int nb = 0; nb < 4; nb++) {
                int nrow = wn * 64 + nb * 16 + rB;
                uint32_t bh[4], bl[4];
                LDSM4(bh, sB + SWZ(nrow * 128 + uB * 16));
                LDSM4(bl, sB + SWZ(nrow * 128 + (uB + 4) * 16));
#pragma unroll
                for (int mi = 0; mi < 2; mi++) {
                    MMA16816(acc[mi][nb * 2 + 0], ah[mi], bh[0], bh[1]);
                    MMA16816(acc[mi][nb * 2 + 1], ah[mi], bh[2], bh[3]);
                    MMA16816(acc[mi][nb * 2 + 0], ah[mi], bl[0], bl[1]);
                    MMA16816(acc[mi][nb * 2 + 1], ah[mi], bl[2], bl[3]);
                    MMA16816(acc[mi][nb * 2 + 0], al[mi], bh[0], bh[1]);
                    MMA16816(acc[mi][nb * 2 + 1], al[mi], bh[2], bh[3]);
                }
            }
        }
    };

    ld_chunk(0, 0);
    CP_COMMIT();
    for (int c = 0; c < nch; c++) {
        if (c + 1 < nch) {
            ld_chunk(c + 1, (c + 1) & 1);
            CP_COMMIT();
            CP_WAIT(1);
        } else {
            CP_WAIT(0);
        }
        __syncthreads();
        compute(c & 1);
        __syncthreads();
    }

    // Epilogue
    const int er = lane >> 2;
    const int ec = (lane & 3) * 2;
    const float sc = (SPLIT && bn < 1024) ? 0.125f : 1.0f;  // fold q scale
#pragma unroll
    for (int mi = 0; mi < 2; mi++) {
#pragma unroll
        for (int nj = 0; nj < 8; nj++) {
            int row = bm + wm * 32 + mi * 16 + er;
            int col = bn + wn * 64 + nj * 8 + ec;
            if (SPLIT) {
#pragma unroll
                for (int rr = 0; rr < 2; rr++) {
                    float a0 = acc[mi][nj][rr * 2 + 0] * sc;
                    float a1 = acc[mi][nj][rr * 2 + 1] * sc;
                    __nv_bfloat16 h0 = __float2bfloat16(a0);
                    __nv_bfloat16 h1 = __float2bfloat16(a1);
                    __nv_bfloat16 l0 = __float2bfloat16(a0 - __bfloat162float(h0));
                    __nv_bfloat16 l1 = __float2bfloat16(a1 - __bfloat162float(h1));
                    size_t off = (size_t)(row + rr * 8) * N + col;
                    *(__nv_bfloat162*)(Ch + off) = __nv_bfloat162(h0, h1);
                    *(__nv_bfloat162*)(Cl + off) = __nv_bfloat162(l0, l1);
                }
            } else {
                float2 v0 = make_float2(acc[mi][nj][0], acc[mi][nj][1]);
                float2 v1 = make_float2(acc[mi][nj][2], acc[mi][nj][3]);
                *(float2*)(C + (size_t)row * N + col) = v0;
                *(float2*)(C + (size_t)(row + 8) * N + col) = v1;
            }
        }
    }
}

// ---------------------------------------------------------------------------
// HMMA flash attention (causal). CTA = 128 q rows, 8 warps (16 rows each).
// K/V chunks of 64 keys, double-buffered cp.async from bf16 hi/lo qkv planes.
// S = Qh*Kh + Qh*Kl + Ql*Kh (Q pre-scaled by 1/8); softmax fp32 in registers;
// O += Ph*Vh + Ph*Vl + Pl*Vh with P split in-register; V^T via ldmatrix.trans.
// Writes yh/yl bf16 planes.
// ---------------------------------------------------------------------------
#define AQH 0
#define AQL 16384
#define AST(s) (32768 + (s) * 32768)   // stage: KH +0, KL +8192, VH +16384, VL +24576
#define ATTN_SMEM (32768 + 2 * 32768)  // 98304

__global__ void __launch_bounds__(256) attn_hmma(
    const __nv_bfloat16* __restrict__ qkvh, const __nv_bfloat16* __restrict__ qkvl,
    __nv_bfloat16* __restrict__ yh, __nv_bfloat16* __restrict__ yl) {
    extern __shared__ char smem[];
    const uint32_t sb = smem_to_u32(smem);
    const int qt = blockIdx.x;
    const int h  = blockIdx.y;
    const int b  = blockIdx.z;
    const int tid = threadIdx.x;
    const int lane = tid & 31;
    const int wid = tid >> 5;

    const size_t tok0 = (size_t)b * TT;

    // ---- Q tile load (128 rows x 64 d, hi+lo) ----
    {
        const int u = tid & 7;
        const int r = tid >> 3;
#pragma unroll
        for (int p = 0; p < 2; p++) {
            const __nv_bfloat16* gq =
                (p ? qkvl : qkvh) + (tok0 + (size_t)qt * 128) * C3 + h * DD + u * 8;
            const uint32_t sq = sb + (p ? AQL : AQH);
#pragma unroll
            for (int it = 0; it < 4; it++) {
                int row = r + it * 32;
                cp16(sq + SWZ(row * 128 + u * 16), gq + (size_t)row * C3);
            }
        }
    }

    auto ld_kv = [&](int kc, int st) {
        const int u = tid & 7;
        const int r = tid >> 3;
        const uint32_t sst = sb + AST(st);
        const size_t trow = tok0 + (size_t)kc * 64;
#pragma unroll
        for (int p = 0; p < 4; p++) {   // KH, KL, VH, VL
            const __nv_bfloat16* g = ((p & 1) ? qkvl : qkvh) + trow * C3 +
                                     ((p < 2) ? CC : 2 * CC) + h * DD + u * 8;
            const uint32_t sdst = sst + p * 8192;
#pragma unroll
            for (int it = 0; it < 2; it++) {
                int row = r + it * 32;
                cp16(sdst + SWZ(row * 128 + u * 16), g + (size_t)row * C3);
            }
        }
    };

    const int nch = 2 * qt + 2;
    ld_kv(0, 0);
    CP_COMMIT();
    if (nch > 1) { ld_kv(1, 1); CP_COMMIT(); }

    uint32_t qh[4][4], ql[4][4];
    float o[8][4];
#pragma unroll
    for (int j = 0; j < 8; j++)
#pragma unroll
        for (int t = 0; t < 4; t++) o[j][t] = 0.f;
    float m0 = -1e30f, m1 = -1e30f, l0 = 0.f, l1 = 0.f;

    const int qrow_lo = qt * 128 + wid * 16;         // warp's first q row
    const int r0 = lane >> 2;                         // accum row (and +8)
    const int c0 = (lane & 3) * 2;                    // accum col pair base

    for (int kc = 0; kc < nch; kc++) {
        if (kc + 1 < nch) CP_WAIT(1); else CP_WAIT(0);
        __syncthreads();

        if (kc == 0) {
            // Q fragments (persistent)
#pragma unroll
            for (int ks = 0; ks < 4; ks++) {
                const int rA = lane & 15;
                const int uA = ks * 2 + (lane >> 4);
                uint32_t a = SWZ((wid * 16 + rA) * 128 + uA * 16);
                LDSM4(qh[ks], sb + AQH + a);
                LDSM4(ql[ks], sb + AQL + a);
            }
        }

        // Skip compute if this chunk is entirely above this warp's diagonal
        if (kc * 64 <= qrow_lo + 15) {
            const uint32_t sK  = sb + AST(kc & 1);
            const uint32_t sKl = sK + 8192;
            const uint32_t sV  = sK + 16384;
            const uint32_t sVl = sK + 24576;

            // ---- S = Q @ K^T ----
            float s[8][4];
#pragma unroll
            for (int j = 0; j < 8; j++)
#pragma unroll
                for (int t = 0; t < 4; t++) s[j][t] = 0.f;

            const int rB = (lane & 7) + ((lane & 16) >> 1);
#pragma unroll
            for (int ks = 0; ks < 4; ks++) {
                const int uB = ks * 2 + ((lane & 8) >> 3);
#pragma unroll
                for (int nb = 0; nb < 4; nb++) {
                    uint32_t kh4[4], kl4[4];
                    uint32_t a = SWZ((nb * 16 + rB) * 128 + uB * 16);
                    LDSM4(kh4, sK + a);
                    LDSM4(kl4, sKl + a);
                    MMA16816(s[nb * 2 + 0], qh[ks], kh4[0], kh4[1]);
                    MMA16816(s[nb * 2 + 1], qh[ks], kh4[2], kh4[3]);
                    MMA16816(s[nb * 2 + 0], qh[ks], kl4[0], kl4[1]);
                    MMA16816(s[nb * 2 + 1], qh[ks], kl4[2], kl4[3]);
                    MMA16816(s[nb * 2 + 0], ql[ks], kh4[0], kh4[1]);
                    MMA16816(s[nb * 2 + 1], ql[ks], kh4[2], kh4[3]);
                }
            }

            // ---- causal mask (only near diagonal) ----
            if (kc * 64 + 63 > qrow_lo) {
                const int qr0 = qrow_lo + r0;
#pragma unroll
                for (int j = 0; j < 8; j++) {
                    int kcol = kc * 64 + 8 * j + c0;
                    if (kcol > qr0)     s[j][0] = -1e30f;
                    if (kcol + 1 > qr0) s[j][1] = -1e30f;
                    if (kcol > qr0 + 8)     s[j][2] = -1e30f;
                    if (kcol + 1 > qr0 + 8) s[j][3] = -1e30f;
                }
            }

            // ---- online softmax (rows r0, r0+8) ----
            float mx0 = -1e30f, mx1 = -1e30f;
#pragma unroll
            for (int j = 0; j < 8; j++) {
                mx0 = fmaxf(mx0, fmaxf(s[j][0], s[j][1]));
                mx1 = fmaxf(mx1, fmaxf(s[j][2], s[j][3]));
            }
            mx0 = fmaxf(mx0, __shfl_xor_sync(0xffffffffu, mx0, 1));
            mx0 = fmaxf(mx0, __shfl_xor_sync(0xffffffffu, mx0, 2));
            mx1 = fmaxf(mx1, __shfl_xor_sync(0xffffffffu, mx1, 1));
            mx1 = fmaxf(mx1, __shfl_xor_sync(0xffffffffu, mx1, 2));
            float mn0 = fmaxf(m0, mx0);
            float mn1 = fmaxf(m1, mx1);
            float corr0 = __expf(m0 - mn0);
            float corr1 = __expf(m1 - mn1);
            float ls0 = 0.f, ls1 = 0.f;
#pragma unroll
            for (int j = 0; j < 8; j++) {
                s[j][0] = __expf(s[j][0] - mn0);
                s[j][1] = __expf(s[j][1] - mn0);
                s[j][2] = __expf(s[j][2] - mn1);
                s[j][3] = __expf(s[j][3] - mn1);
                ls0 += s[j][0] + s[j][1];
                ls1 += s[j][2] + s[j][3];
            }
            ls0 += __shfl_xor_sync(0xffffffffu, ls0, 1);
            ls0 += __shfl_xor_sync(0xffffffffu, ls0, 2);
            ls1 += __shfl_xor_sync(0xffffffffu, ls1, 1);
            ls1 += __shfl_xor_sync(0xffffffffu, ls1, 2);
            l0 = l0 * corr0 + ls0;
            l1 = l1 * corr1 + ls1;
            m0 = mn0; m1 = mn1;
#pragma unroll
            for (int j = 0; j < 8; j++) {
                o[j][0] *= corr0; o[j][1] *= corr0;
                o[j][2] *= corr1; o[j][3] *= corr1;
            }

            // ---- pack P into A fragments (hi/lo) ----
            uint32_t ph[4][4], pl[4][4];
#pragma unroll
            for (int ks = 0; ks < 4; ks++) {
                const int j0 = 2 * ks, j1 = 2 * ks + 1;
                float v0 = s[j0][0], v1 = s[j0][1], v2 = s[j0][2], v3 = s[j0][3];
                float w0 = s[j1][0], w1 = s[j1][1], w2 = s[j1][2], w3 = s[j1][3];
                ph[ks][0] = pack_bf16x2(v0, v1);
                ph[ks][1] = pack_bf16x2(v2, v3);
                ph[ks][2] = pack_bf16x2(w0, w1);
                ph[ks][3] = pack_bf16x2(w2, w3);
                __nv_bfloat162 h;
                h = *(__nv_bfloat162*)&ph[ks][0];
                pl[ks][0] = pack_bf16x2(v0 - __bfloat162float(h.x), v1 - __bfloat162float(h.y));
                h = *(__nv_bfloat162*)&ph[ks][1];
                pl[ks][1] = pack_bf16x2(v2 - __bfloat162float(h.x), v3 - __bfloat162float(h.y));
                h = *(__nv_bfloat162*)&ph[ks][2];
                pl[ks][2] = pack_bf16x2(w0 - __bfloat162float(h.x), w1 - __bfloat162float(h.y));
                h = *(__nv_bfloat162*)&ph[ks][3];
                pl[ks][3] = pack_bf16x2(w2 - __bfloat162float(h.x), w3 - __bfloat162float(h.y));
            }

            // ---- O += P @ V (V^T fragments via ldmatrix.trans) ----
#pragma unroll
            for (int ks = 0; ks < 4; ks++) {
#pragma unroll
                for (int db = 0; db < 4; db++) {
                    uint32_t vh4[4], vl4[4];
                    uint32_t a = SWZ((ks * 16 + (lane & 7) + ((lane >> 3) & 1) * 8) * 128 +
                                     ((lane >> 4) + db * 2) * 16);
                    LDSM4T(vh4, sV + a);
                    LDSM4T(vl4, sVl + a);
                    MMA16816(o[db * 2 + 0], ph[ks], vh4[0], vh4[1]);
                    MMA16816(o[db * 2 + 1], ph[ks], vh4[2], vh4[3]);
                    MMA16816(o[db * 2 + 0], ph[ks], vl4[0], vl4[1]);
                    MMA16816(o[db * 2 + 1], ph[ks], vl4[2], vl4[3]);
                    MMA16816(o[db * 2 + 0], pl[ks], vh4[0], vh4[1]);
                    MMA16816(o[db * 2 + 1], pl[ks], vh4[2], vh4[3]);
                }
            }
        }

        __syncthreads();
        if (kc + 2 < nch) {
            ld_kv(kc + 2, kc & 1);
            CP_COMMIT();
        }
    }

    // ---- epilogue: normalize, split hi/lo, write yh/yl ----
    const float i0 = 1.f / l0;
    const float i1 = 1.f / l1;
    const size_t tokA = tok0 + (size_t)qt * 128 + wid * 16 + r0;
#pragma unroll
    for (int j = 0; j < 8; j++) {
        int dc = h * DD + 8 * j + c0;
        float a0 = o[j][0] * i0, a1 = o[j][1] * i0;
        float b0 = o[j][2] * i1, b1 = o[j][3] * i1;
        __nv_bfloat16 h0 = __float2bfloat16(a0), h1 = __float2bfloat16(a1);
        __nv_bfloat16 h2 = __float2bfloat16(b0), h3 = __float2bfloat16(b1);
        size_t offA = tokA * CC + dc;
        size_t offB = (tokA + 8) * CC + dc;
        *(__nv_bfloat162*)(yh + offA) = __nv_bfloat162(h0, h1);
        *(__nv_bfloat162*)(yh + offB) = __nv_bfloat162(h2, h3);
        *(__nv_bfloat162*)(yl + offA) = __nv_bfloat162(
            __float2bfloat16(a0 - __bfloat162float(h0)),
            __float2bfloat16(a1 - __bfloat162float(h1)));
        *(__nv_bfloat162*)(yl + offB) = __nv_bfloat162(
            __float2bfloat16(b0 - __bfloat162float(h2)),
            __float2bfloat16(b1 - __bfloat162float(h3)));
    }
}

// ---------------------------------------------------------------------------
extern "C" void kernel_launch(void* const* d_in, const int* in_sizes, int n_in,
                              void* d_out, int out_size) {
    const float* x      = (const float*)d_in[0];
    const float* w_attn = (const float*)d_in[1];
    const float* w_proj = (const float*)d_in[2];
    float* out = (float*)d_out;

    void *xh_p, *xl_p, *wah_p, *wal_p, *wph_p, *wpl_p, *qh_p, *ql_p, *yh_p, *yl_p;
    cudaGetSymbolAddress(&xh_p, g_xh);
    cudaGetSymbolAddress(&xl_p, g_xl);
    cudaGetSymbolAddress(&wah_p, g_wah);
    cudaGetSymbolAddress(&wal_p, g_wal);
    cudaGetSymbolAddress(&wph_p, g_wph);
    cudaGetSymbolAddress(&wpl_p, g_wpl);
    cudaGetSymbolAddress(&qh_p, g_qkvh);
    cudaGetSymbolAddress(&ql_p, g_qkvl);
    cudaGetSymbolAddress(&yh_p, g_yh);
    cudaGetSymbolAddress(&yl_p, g_yl);

    cudaFuncSetAttribute(gemm_hmma3<true>,
                         cudaFuncAttributeMaxDynamicSharedMemorySize, GEMM_SMEM);
    cudaFuncSetAttribute(gemm_hmma3<false>,
                         cudaFuncAttributeMaxDynamicSharedMemorySize, GEMM_SMEM);
    cudaFuncSetAttribute(attn_hmma,
                         cudaFuncAttributeMaxDynamicSharedMemorySize, ATTN_SMEM);

    // 1) Splits
    split_f32<<<(MM * CC / 4 + 255) / 256, 256>>>(x, (__nv_bfloat16*)xh_p,
                                                  (__nv_bfloat16*)xl_p, MM * CC / 4);
    split_f32<<<(C3 * CC / 4 + 255) / 256, 256>>>(w_attn, (__nv_bfloat16*)wah_p,
                                                  (__nv_bfloat16*)wal_p, C3 * CC / 4);
    split_f32<<<(CC * CC / 4 + 255) / 256, 256>>>(w_proj, (__nv_bfloat16*)wph_p,
                                                  (__nv_bfloat16*)wpl_p, CC * CC / 4);

    // 2) QKV gemm -> bf16 hi/lo planes (q pre-scaled by 1/8)
    gemm_hmma3<true><<<dim3(C3 / 128, MM / 128), 256, GEMM_SMEM>>>(
        (const __nv_bfloat16*)xh_p, (const __nv_bfloat16*)xl_p,
        (const __nv_bfloat16*)wah_p, (const __nv_bfloat16*)wal_p,
        nullptr, (__nv_bfloat16*)qh_p, (__nv_bfloat16*)ql_p, MM, C3, CC);

    // 3) HMMA flash attention -> yh/yl
    attn_hmma<<<dim3(TT / 128, HH, BB), 256, ATTN_SMEM>>>(
        (const __nv_bfloat16*)qh_p, (const __nv_bfloat16*)ql_p,
        (__nv_bfloat16*)yh_p, (__nv_bfloat16*)yl_p);

    // 4) out = y @ w_proj^T (fp32)
    gemm_hmma3<false><<<dim3(CC / 128, MM / 128), 256, GEMM_SMEM>>>(
        (const __nv_bfloat16*)yh_p, (const __nv_bfloat16*)yl_p,
        (const __nv_bfloat16*)wph_p, (const __nv_bfloat16*)wpl_p,
        out, nullptr, nullptr, MM, CC, CC);
}

// round 6
// speedup vs baseline: 2.6271x; 1.0217x over previous
#include <cuda_runtime.h>
#include <cuda_bf16.h>
#include <cstdint>
#include <math.h>

// Problem dims
#define BB 2
#define TT 2048
#define CC 1024
#define HH 16
#define DD 64
#define C3 3072
#define MM (BB * TT)   // 4096

// ---------------------------------------------------------------------------
// Scratch (device globals; no allocation allowed)
// ---------------------------------------------------------------------------
__device__ __nv_bfloat16 g_xh[(size_t)MM * CC];
__device__ __nv_bfloat16 g_xl[(size_t)MM * CC];
__device__ __nv_bfloat16 g_wah[(size_t)C3 * CC];
__device__ __nv_bfloat16 g_wal[(size_t)C3 * CC];
__device__ __nv_bfloat16 g_wph[(size_t)CC * CC];
__device__ __nv_bfloat16 g_wpl[(size_t)CC * CC];
__device__ __nv_bfloat16 g_qkvh[(size_t)MM * C3];
__device__ __nv_bfloat16 g_qkvl[(size_t)MM * C3];
__device__ __nv_bfloat16 g_yh[(size_t)MM * CC];
__device__ __nv_bfloat16 g_yl[(size_t)MM * CC];

// ---------------------------------------------------------------------------
// Helpers (sm_103 base-target: ldmatrix / mma.sync / cp.async)
// ---------------------------------------------------------------------------
__device__ __forceinline__ uint32_t smem_to_u32(const void* p) {
    uint32_t a;
    asm("{ .reg .u64 t; cvta.to.shared.u64 t, %1; cvt.u32.u64 %0, t; }"
        : "=r"(a) : "l"(p));
    return a;
}

#define SWZ(off) ((off) ^ (((off) >> 3) & 0x70))

__device__ __forceinline__ void cp16(uint32_t saddr, const void* g) {
    asm volatile("cp.async.cg.shared.global [%0], [%1], 16;"
                 :: "r"(saddr), "l"(g));
}
#define CP_COMMIT() asm volatile("cp.async.commit_group;" ::: "memory")
#define CP_WAIT(n)  asm volatile("cp.async.wait_group %0;" :: "n"(n) : "memory")

#define LDSM4(r, addr) \
    asm volatile("ldmatrix.sync.aligned.m8n8.x4.shared.b16 {%0,%1,%2,%3}, [%4];" \
        : "=r"((r)[0]), "=r"((r)[1]), "=r"((r)[2]), "=r"((r)[3]) : "r"(addr))

#define LDSM4T(r, addr) \
    asm volatile("ldmatrix.sync.aligned.m8n8.x4.trans.shared.b16 {%0,%1,%2,%3}, [%4];" \
        : "=r"((r)[0]), "=r"((r)[1]), "=r"((r)[2]), "=r"((r)[3]) : "r"(addr))

#define MMA16816(d, a, b0v, b1v) \
    asm volatile("mma.sync.aligned.m16n8k16.row.col.f32.bf16.bf16.f32 " \
        "{%0,%1,%2,%3}, {%4,%5,%6,%7}, {%8,%9}, {%0,%1,%2,%3};" \
        : "+f"((d)[0]), "+f"((d)[1]), "+f"((d)[2]), "+f"((d)[3]) \
        : "r"((a)[0]), "r"((a)[1]), "r"((a)[2]), "r"((a)[3]), "r"(b0v), "r"(b1v))

__device__ __forceinline__ uint32_t pack_bf16x2(float a, float b) {
    __nv_bfloat162 t = __floats2bfloat162_rn(a, b);
    return *(uint32_t*)&t;
}

// ---------------------------------------------------------------------------
// Split fp32 -> bf16 hi/lo planes
// ---------------------------------------------------------------------------
__global__ void __launch_bounds__(256) split_f32(const float* __restrict__ in,
                                                 __nv_bfloat16* __restrict__ hi,
                                                 __nv_bfloat16* __restrict__ lo,
                                                 int n4) {
    int i = blockIdx.x * 256 + threadIdx.x;
    if (i >= n4) return;
    float4 v = ((const float4*)in)[i];
    __nv_bfloat16 h0 = __float2bfloat16(v.x);
    __nv_bfloat16 h1 = __float2bfloat16(v.y);
    __nv_bfloat16 h2 = __float2bfloat16(v.z);
    __nv_bfloat16 h3 = __float2bfloat16(v.w);
    __nv_bfloat16 l0 = __float2bfloat16(v.x - __bfloat162float(h0));
    __nv_bfloat16 l1 = __float2bfloat16(v.y - __bfloat162float(h1));
    __nv_bfloat16 l2 = __float2bfloat16(v.z - __bfloat162float(h2));
    __nv_bfloat16 l3 = __float2bfloat16(v.w - __bfloat162float(h3));
    ((__nv_bfloat162*)hi)[i * 2 + 0] = __nv_bfloat162(h0, h1);
    ((__nv_bfloat162*)hi)[i * 2 + 1] = __nv_bfloat162(h2, h3);
    ((__nv_bfloat162*)lo)[i * 2 + 0] = __nv_bfloat162(l0, l1);
    ((__nv_bfloat162*)lo)[i * 2 + 1] = __nv_bfloat162(l2, l3);
}

// ---------------------------------------------------------------------------
// HMMA GEMM: C[M,N] = A[M,K] @ B[N,K]^T, fp32-accurate via bf16 3-term split.
// Tile 128x128, K-chunk 32, 512 threads (16 warps = 4m x 4n), warp tile 32x32.
// 4-stage cp.async pipeline, one __syncthreads per chunk.
// SPLIT=true: write bf16 hi/lo planes (scaling cols<1024 by 0.125 for Q).
// ---------------------------------------------------------------------------
#define NSTAGE 4
#define STAGE_BYTES 32768
#define GEMM_SMEM (NSTAGE * STAGE_BYTES)   // 131072

template <bool SPLIT>
__global__ void __launch_bounds__(512) gemm_hmma3(
    const __nv_bfloat16* __restrict__ Ah, const __nv_bfloat16* __restrict__ Al,
    const __nv_bfloat16* __restrict__ Bh, const __nv_bfloat16* __restrict__ Bl,
    float* __restrict__ C, __nv_bfloat16* __restrict__ Ch,
    __nv_bfloat16* __restrict__ Cl, int M, int N, int K) {
    extern __shared__ char smem[];
    const uint32_t sbase = smem_to_u32(smem);
    const int tid = threadIdx.x;
    const int lane = tid & 31;
    const int wid = tid >> 5;      // 0..15
    const int wm = wid >> 2;       // 0..3
    const int wn = wid & 3;        // 0..3
    const int bm = blockIdx.y * 128;
    const int bn = blockIdx.x * 128;

    float acc[2][4][4];
#pragma unroll
    for (int i = 0; i < 2; i++)
#pragma unroll
        for (int j = 0; j < 4; j++)
#pragma unroll
            for (int t = 0; t < 4; t++) acc[i][j][t] = 0.f;

    const int nch = K >> 5;
    const int rowL = tid >> 3;     // 0..63
    const int uL = tid & 7;        // 16B unit: 0-3 hi plane, 4-7 lo plane

    auto ld_chunk = [&](int c, int st) {
        const int k0 = c << 5;
        const uint32_t sA = sbase + st * STAGE_BYTES;
        const uint32_t sB = sA + 16384;
        const int kk = k0 + (uL & 3) * 8;
        const bool isHi = (uL < 4);
        const __nv_bfloat16* gA = (isHi ? Ah : Al);
        const __nv_bfloat16* gB = (isHi ? Bh : Bl);
#pragma unroll
        for (int it = 0; it < 2; it++) {
            int row = rowL + it * 64;
            cp16(sA + SWZ(row * 128 + uL * 16), gA + (size_t)(bm + row) * K + kk);
            cp16(sB + SWZ(row * 128 + uL * 16), gB + (size_t)(bn + row) * K + kk);
        }
    };

    auto compute = [&](int st) {
        const uint32_t sA = sbase + st * STAGE_BYTES;
        const uint32_t sB = sA + 16384;
#pragma unroll
        for (int ks = 0; ks < 2; ks++) {
            uint32_t ah[2][4], al[2][4];
            const int rA = lane & 15;
            const int uA = ks * 2 + (lane >> 4);
#pragma unroll
            for (int mi = 0; mi < 2; mi++) {
                int mrow = wm * 32 + mi * 16 + rA;
                LDSM4(ah[mi], sA + SWZ(mrow * 128 + uA * 16));
                LDSM4(al[mi], sA + SWZ(mrow * 128 + (uA + 4) * 16));
            }
            const int rB = (lane & 7) + ((lane & 16) >> 1);
            const int uB = ks * 2 + ((lane & 8) >> 3);
#pragma unroll
            for (int nb = 0; nb < 2; nb++) {
                int nrow = wn * 32 + nb * 16 + rB;
                uint32_t bh[4], bl[4];
                LDSM4(bh, sB + SWZ(nrow * 128 + uB * 16));
                LDSM4(bl, sB + SWZ(nrow * 128 + (uB + 4) * 16));
#pragma unroll
                for (int mi = 0; mi < 2; mi++) {
                    MMA16816(acc[mi][nb * 2 + 0], ah[mi], bh[0], bh[1]);
                    MMA16816(acc[mi][nb * 2 + 1], ah[mi], bh[2], bh[3]);
                    MMA16816(acc[mi][nb * 2 + 0], ah[mi], bl[0], bl[1]);
                    MMA16816(acc[mi][nb * 2 + 1], ah[mi], bl[2], bl[3]);
                    MMA16816(acc[mi][nb * 2 + 0], al[mi], bh[0], bh[1]);
                    MMA16816(acc[mi][nb * 2 + 1], al[mi], bh[2], bh[3]);
                }
            }
        }
    };

    // 3-deep prologue (nch is always 32 here)
    ld_chunk(0, 0); CP_COMMIT();
    ld_chunk(1, 1); CP_COMMIT();
    ld_chunk(2, 2); CP_COMMIT();

    for (int c = 0; c < nch; c++) {
        if (c < nch - 2)       CP_WAIT(2);
        else if (c == nch - 2) CP_WAIT(1);
        else                   CP_WAIT(0);
        __syncthreads();
        compute(c & 3);
        if (c + 3 < nch) {
            ld_chunk(c + 3, (c + 3) & 3);
            CP_COMMIT();
        }
    }

    // Epilogue
    const int er = lane >> 2;
    const int ec = (lane & 3) * 2;
    const float sc = (SPLIT && bn < 1024) ? 0.125f : 1.0f;  // fold q scale
#pragma unroll
    for (int mi = 0; mi < 2; mi++) {
#pragma unroll
        for (int nj = 0; nj < 4; nj++) {
            int row = bm + wm * 32 + mi * 16 + er;
            int col = bn + wn * 32 + nj * 8 + ec;
            if (SPLIT) {
#pragma unroll
                for (int rr = 0; rr < 2; rr++) {
                    float a0 = acc[mi][nj][rr * 2 + 0] * sc;
                    float a1 = acc[mi][nj][rr * 2 + 1] * sc;
                    __nv_bfloat16 h0 = __float2bfloat16(a0);
                    __nv_bfloat16 h1 = __float2bfloat16(a1);
                    __nv_bfloat16 l0 = __float2bfloat16(a0 - __bfloat162float(h0));
                    __nv_bfloat16 l1 = __float2bfloat16(a1 - __bfloat162float(h1));
                    size_t off = (size_t)(row + rr * 8) * N + col;
                    *(__nv_bfloat162*)(Ch + off) = __nv_bfloat162(h0, h1);
                    *(__nv_bfloat162*)(Cl + off) = __nv_bfloat162(l0, l1);
                }
            } else {
                float2 v0 = make_float2(acc[mi][nj][0], acc[mi][nj][1]);
                float2 v1 = make_float2(acc[mi][nj][2], acc[mi][nj][3]);
                *(float2*)(C + (size_t)row * N + col) = v0;
                *(float2*)(C + (size_t)(row + 8) * N + col) = v1;
            }
        }
    }
}

// ---------------------------------------------------------------------------
// HMMA flash attention (causal). CTA = 128 q rows, 8 warps (16 rows each).
// Unchanged from round 4 (passes, ~200us).
// ---------------------------------------------------------------------------
#define AQH 0
#define AQL 16384
#define AST(s) (32768 + (s) * 32768)   // stage: KH +0, KL +8192, VH +16384, VL +24576
#define ATTN_SMEM (32768 + 2 * 32768)  // 98304

__global__ void __launch_bounds__(256) attn_hmma(
    const __nv_bfloat16* __restrict__ qkvh, const __nv_bfloat16* __restrict__ qkvl,
    __nv_bfloat16* __restrict__ yh, __nv_bfloat16* __restrict__ yl) {
    extern __shared__ char smem[];
    const uint32_t sb = smem_to_u32(smem);
    const int qt = blockIdx.x;
    const int h  = blockIdx.y;
    const int b  = blockIdx.z;
    const int tid = threadIdx.x;
    const int lane = tid & 31;
    const int wid = tid >> 5;

    const size_t tok0 = (size_t)b * TT;

    // ---- Q tile load (128 rows x 64 d, hi+lo) ----
    {
        const int u = tid & 7;
        const int r = tid >> 3;
#pragma unroll
        for (int p = 0; p < 2; p++) {
            const __nv_bfloat16* gq =
                (p ? qkvl : qkvh) + (tok0 + (size_t)qt * 128) * C3 + h * DD + u * 8;
            const uint32_t sq = sb + (p ? AQL : AQH);
#pragma unroll
            for (int it = 0; it < 4; it++) {
                int row = r + it * 32;
                cp16(sq + SWZ(row * 128 + u * 16), gq + (size_t)row * C3);
            }
        }
    }

    auto ld_kv = [&](int kc, int st) {
        const int u = tid & 7;
        const int r = tid >> 3;
        const uint32_t sst = sb + AST(st);
        const size_t trow = tok0 + (size_t)kc * 64;
#pragma unroll
        for (int p = 0; p < 4; p++) {   // KH, KL, VH, VL
            const __nv_bfloat16* g = ((p & 1) ? qkvl : qkvh) + trow * C3 +
                                     ((p < 2) ? CC : 2 * CC) + h * DD + u * 8;
            const uint32_t sdst = sst + p * 8192;
#pragma unroll
            for (int it = 0; it < 2; it++) {
                int row = r + it * 32;
                cp16(sdst + SWZ(row * 128 + u * 16), g + (size_t)row * C3);
            }
        }
    };

    const int nch = 2 * qt + 2;
    ld_kv(0, 0);
    CP_COMMIT();
    if (nch > 1) { ld_kv(1, 1); CP_COMMIT(); }

    uint32_t qh[4][4], ql[4][4];
    float o[8][4];
#pragma unroll
    for (int j = 0; j < 8; j++)
#pragma unroll
        for (int t = 0; t < 4; t++) o[j][t] = 0.f;
    float m0 = -1e30f, m1 = -1e30f, l0 = 0.f, l1 = 0.f;

    const int qrow_lo = qt * 128 + wid * 16;
    const int r0 = lane >> 2;
    const int c0 = (lane & 3) * 2;

    for (int kc = 0; kc < nch; kc++) {
        if (kc + 1 < nch) CP_WAIT(1); else CP_WAIT(0);
        __syncthreads();

        if (kc == 0) {
#pragma unroll
            for (int ks = 0; ks < 4; ks++) {
                const int rA = lane & 15;
                const int uA = ks * 2 + (lane >> 4);
                uint32_t a = SWZ((wid * 16 + rA) * 128 + uA * 16);
                LDSM4(qh[ks], sb + AQH + a);
                LDSM4(ql[ks], sb + AQL + a);
            }
        }

        if (kc * 64 <= qrow_lo + 15) {
            const uint32_t sK  = sb + AST(kc & 1);
            const uint32_t sKl = sK + 8192;
            const uint32_t sV  = sK + 16384;
            const uint32_t sVl = sK + 24576;

            float s[8][4];
#pragma unroll
            for (int j = 0; j < 8; j++)
#pragma unroll
                for (int t = 0; t < 4; t++) s[j][t] = 0.f;

            const int rB = (lane & 7) + ((lane & 16) >> 1);
#pragma unroll
            for (int ks = 0; ks < 4; ks++) {
                const int uB = ks * 2 + ((lane & 8) >> 3);
#pragma unroll
                for (int nb = 0; nb < 4; nb++) {
                    uint32_t kh4[4], kl4[4];
                    uint32_t a = SWZ((nb * 16 + rB) * 128 + uB * 16);
                    LDSM4(kh4, sK + a);
                    LDSM4(kl4, sKl + a);
                    MMA16816(s[nb * 2 + 0], qh[ks], kh4[0], kh4[1]);
                    MMA16816(s[nb * 2 + 1], qh[ks], kh4[2], kh4[3]);
                    MMA16816(s[nb * 2 + 0], qh[ks], kl4[0], kl4[1]);
                    MMA16816(s[nb * 2 + 1], qh[ks], kl4[2], kl4[3]);
                    MMA16816(s[nb * 2 + 0], ql[ks], kh4[0], kh4[1]);
                    MMA16816(s[nb * 2 + 1], ql[ks], kh4[2], kh4[3]);
                }
            }

            if (kc * 64 + 63 > qrow_lo) {
                const int qr0 = qrow_lo + r0;
#pragma unroll
                for (int j = 0; j < 8; j++) {
                    int kcol = kc * 64 + 8 * j + c0;
                    if (kcol > qr0)     s[j][0] = -1e30f;
                    if (kcol + 1 > qr0) s[j][1] = -1e30f;
                    if (kcol > qr0 + 8)     s[j][2] = -1e30f;
                    if (kcol + 1 > qr0 + 8) s[j][3] = -1e30f;
                }
            }

            float mx0 = -1e30f, mx1 = -1e30f;
#pragma unroll
            for (int j = 0; j < 8; j++) {
                mx0 = fmaxf(mx0, fmaxf(s[j][0], s[j][1]));
                mx1 = fmaxf(mx1, fmaxf(s[j][2], s[j][3]));
            }
            mx0 = fmaxf(mx0, __shfl_xor_sync(0xffffffffu, mx0, 1));
            mx0 = fmaxf(mx0, __shfl_xor_sync(0xffffffffu, mx0, 2));
            mx1 = fmaxf(mx1, __shfl_xor_sync(0xffffffffu, mx1, 1));
            mx1 = fmaxf(mx1, __shfl_xor_sync(0xffffffffu, mx1, 2));
            float mn0 = fmaxf(m0, mx0);
            float mn1 = fmaxf(m1, mx1);
            float corr0 = __expf(m0 - mn0);
            float corr1 = __expf(m1 - mn1);
            float ls0 = 0.f, ls1 = 0.f;
#pragma unroll
            for (int j = 0; j < 8; j++) {
                s[j][0] = __expf(s[j][0] - mn0);
                s[j][1] = __expf(s[j][1] - mn0);
                s[j][2] = __expf(s[j][2] - mn1);
                s[j][3] = __expf(s[j][3] - mn1);
                ls0 += s[j][0] + s[j][1];
                ls1 += s[j][2] + s[j][3];
            }
            ls0 += __shfl_xor_sync(0xffffffffu, ls0, 1);
            ls0 += __shfl_xor_sync(0xffffffffu, ls0, 2);
            ls1 += __shfl_xor_sync(0xffffffffu, ls1, 1);
            ls1 += __shfl_xor_sync(0xffffffffu, ls1, 2);
            l0 = l0 * corr0 + ls0;
            l1 = l1 * corr1 + ls1;
            m0 = mn0; m1 = mn1;
#pragma unroll
            for (int j = 0; j < 8; j++) {
                o[j][0] *= corr0; o[j][1] *= corr0;
                o[j][2] *= corr1; o[j][3] *= corr1;
            }

            uint32_t ph[4][4], pl[4][4];
#pragma unroll
            for (int ks = 0; ks < 4; ks++) {
                const int j0 = 2 * ks, j1 = 2 * ks + 1;
                float v0 = s[j0][0], v1 = s[j0][1], v2 = s[j0][2], v3 = s[j0][3];
                float w0 = s[j1][0], w1 = s[j1][1], w2 = s[j1][2], w3 = s[j1][3];
                ph[ks][0] = pack_bf16x2(v0, v1);
                ph[ks][1] = pack_bf16x2(v2, v3);
                ph[ks][2] = pack_bf16x2(w0, w1);
                ph[ks][3] = pack_bf16x2(w2, w3);
                __nv_bfloat162 hh;
                hh = *(__nv_bfloat162*)&ph[ks][0];
                pl[ks][0] = pack_bf16x2(v0 - __bfloat162float(hh.x), v1 - __bfloat162float(hh.y));
                hh = *(__nv_bfloat162*)&ph[ks][1];
                pl[ks][1] = pack_bf16x2(v2 - __bfloat162float(hh.x), v3 - __bfloat162float(hh.y));
                hh = *(__nv_bfloat162*)&ph[ks][2];
                pl[ks][2] = pack_bf16x2(w0 - __bfloat162float(hh.x), w1 - __bfloat162float(hh.y));
                hh = *(__nv_bfloat162*)&ph[ks][3];
                pl[ks][3] = pack_bf16x2(w2 - __bfloat162float(hh.x), w3 - __bfloat162float(hh.y));
            }

#pragma unroll
            for (int ks = 0; ks < 4; ks++) {
#pragma unroll
                for (int db = 0; db < 4; db++) {
                    uint32_t vh4[4], vl4[4];
                    uint32_t a = SWZ((ks * 16 + (lane & 7) + ((lane >> 3) & 1) * 8) * 128 +
                                     ((lane >> 4) + db * 2) * 16);
                    LDSM4T(vh4, sV + a);
                    LDSM4T(vl4, sVl + a);
                    MMA16816(o[db * 2 + 0], ph[ks], vh4[0], vh4[1]);
                    MMA16816(o[db * 2 + 1], ph[ks], vh4[2], vh4[3]);
                    MMA16816(o[db * 2 + 0], ph[ks], vl4[0], vl4[1]);
                    MMA16816(o[db * 2 + 1], ph[ks], vl4[2], vl4[3]);
                    MMA16816(o[db * 2 + 0], pl[ks], vh4[0], vh4[1]);
                    MMA16816(o[db * 2 + 1], pl[ks], vh4[2], vh4[3]);
                }
            }
        }

        __syncthreads();
        if (kc + 2 < nch) {
            ld_kv(kc + 2, kc & 1);
            CP_COMMIT();
        }
    }

    const float i0 = 1.f / l0;
    const float i1 = 1.f / l1;
    const size_t tokA = tok0 + (size_t)qt * 128 + wid * 16 + r0;
#pragma unroll
    for (int j = 0; j < 8; j++) {
        int dc = h * DD + 8 * j + c0;
        float a0 = o[j][0] * i0, a1 = o[j][1] * i0;
        float b0 = o[j][2] * i1, b1 = o[j][3] * i1;
        __nv_bfloat16 h0 = __float2bfloat16(a0), h1 = __float2bfloat16(a1);
        __nv_bfloat16 h2 = __float2bfloat16(b0), h3 = __float2bfloat16(b1);
        size_t offA = tokA * CC + dc;
        size_t offB = (tokA + 8) * CC + dc;
        *(__nv_bfloat162*)(yh + offA) = __nv_bfloat162(h0, h1);
        *(__nv_bfloat162*)(yh + offB) = __nv_bfloat162(h2, h3);
        *(__nv_bfloat162*)(yl + offA) = __nv_bfloat162(
            __float2bfloat16(a0 - __bfloat162float(h0)),
            __float2bfloat16(a1 - __bfloat162float(h1)));
        *(__nv_bfloat162*)(yl + offB) = __nv_bfloat162(
            __float2bfloat16(b0 - __bfloat162float(h2)),
            __float2bfloat16(b1 - __bfloat162float(h3)));
    }
}

// ---------------------------------------------------------------------------
extern "C" void kernel_launch(void* const* d_in, const int* in_sizes, int n_in,
                              void* d_out, int out_size) {
    const float* x      = (const float*)d_in[0];
    const float* w_attn = (const float*)d_in[1];
    const float* w_proj = (const float*)d_in[2];
    float* out = (float*)d_out;

    void *xh_p, *xl_p, *wah_p, *wal_p, *wph_p, *wpl_p, *qh_p, *ql_p, *yh_p, *yl_p;
    cudaGetSymbolAddress(&xh_p, g_xh);
    cudaGetSymbolAddress(&xl_p, g_xl);
    cudaGetSymbolAddress(&wah_p, g_wah);
    cudaGetSymbolAddress(&wal_p, g_wal);
    cudaGetSymbolAddress(&wph_p, g_wph);
    cudaGetSymbolAddress(&wpl_p, g_wpl);
    cudaGetSymbolAddress(&qh_p, g_qkvh);
    cudaGetSymbolAddress(&ql_p, g_qkvl);
    cudaGetSymbolAddress(&yh_p, g_yh);
    cudaGetSymbolAddress(&yl_p, g_yl);

    cudaFuncSetAttribute(gemm_hmma3<true>,
                         cudaFuncAttributeMaxDynamicSharedMemorySize, GEMM_SMEM);
    cudaFuncSetAttribute(gemm_hmma3<false>,
                         cudaFuncAttributeMaxDynamicSharedMemorySize, GEMM_SMEM);
    cudaFuncSetAttribute(attn_hmma,
                         cudaFuncAttributeMaxDynamicSharedMemorySize, ATTN_SMEM);

    // 1) Splits
    split_f32<<<(MM * CC / 4 + 255) / 256, 256>>>(x, (__nv_bfloat16*)xh_p,
                                                  (__nv_bfloat16*)xl_p, MM * CC / 4);
    split_f32<<<(C3 * CC / 4 + 255) / 256, 256>>>(w_attn, (__nv_bfloat16*)wah_p,
                                                  (__nv_bfloat16*)wal_p, C3 * CC / 4);
    split_f32<<<(CC * CC / 4 + 255) / 256, 256>>>(w_proj, (__nv_bfloat16*)wph_p,
                                                  (__nv_bfloat16*)wpl_p, CC * CC / 4);

    // 2) QKV gemm -> bf16 hi/lo planes (q pre-scaled by 1/8)
    gemm_hmma3<true><<<dim3(C3 / 128, MM / 128), 512, GEMM_SMEM>>>(
        (const __nv_bfloat16*)xh_p, (const __nv_bfloat16*)xl_p,
        (const __nv_bfloat16*)wah_p, (const __nv_bfloat16*)wal_p,
        nullptr, (__nv_bfloat16*)qh_p, (__nv_bfloat16*)ql_p, MM, C3, CC);

    // 3) HMMA flash attention -> yh/yl
    attn_hmma<<<dim3(TT / 128, HH, BB), 256, ATTN_SMEM>>>(
        (const __nv_bfloat16*)qh_p, (const __nv_bfloat16*)ql_p,
        (__nv_bfloat16*)yh_p, (__nv_bfloat16*)yl_p);

    // 4) out = y @ w_proj^T (fp32)
    gemm_hmma3<false><<<dim3(CC / 128, MM / 128), 512, GEMM_SMEM>>>(
        (const __nv_bfloat16*)yh_p, (const __nv_bfloat16*)yl_p,
        (const __nv_bfloat16*)wph_p, (const __nv_bfloat16*)wpl_p,
        out, nullptr, nullptr, MM, CC, CC);
}